// round 11
// baseline (speedup 1.0000x reference)
#include <cuda_runtime.h>
#include <cuda_bf16.h>

#define NB 64      // batch
#define NL 512     // sequence length
#define ND 300     // embed dim
#define ND4 75     // float4 lanes per row
#define NC 128     // channels
#define CH 8       // token chunks per batch
#define TPC 64     // tokens per gather block
#define WAYS 4
#define JPER 16    // tokens per way

// Scratch (__device__ globals per allocation rules)
__device__ float4 g_part4[NB * CH * 3 * ND4];  // partial g sums
__device__ float4 g_W2T4[225 * NC];            // fused conv*fc weights, transposed
__device__ float  g_bias2[NC];                 // fused bias
__device__ float  g_coef[3 * NL];              // per-token window coefficients

// ---------------------------------------------------------------------------
// Kernel 0 (prep): blocks 0..127 -> W2T row-slices + bias2 (one c' each);
// block 128 -> per-token coefficients A_k[t].
// Independent of x/embed; runs before the gather.
// ---------------------------------------------------------------------------
__global__ __launch_bounds__(256) void prep_kernel(
    const float* __restrict__ conv_w,
    const float* __restrict__ conv_b,
    const float* __restrict__ fc3_w,
    const float* __restrict__ fc3_b,
    const float* __restrict__ fc4_w,
    const float* __restrict__ fc4_b,
    const float* __restrict__ fc5_w,
    const float* __restrict__ fc5_b,
    const float* __restrict__ fc_w,
    const float* __restrict__ fc_b)
{
    const int tid  = threadIdx.x;
    const int warp = tid >> 5;
    const int lane = tid & 31;

    if (blockIdx.x == 128) {
        // Coefficients: A_k[t] = sum_{l=max(0,t-k+1)}^{min(t,L-k-1)} wk[l]
        for (int i = tid; i < 3 * NL; i += 256) {
            const int kk = i >> 9;
            const int t  = i & 511;
            const float* wk = (kk == 0) ? fc3_w : (kk == 1) ? fc4_w : fc5_w;
            const int k = kk + 3;
            int lo = t - k + 1; if (lo < 0) lo = 0;
            int hi = t; const int lim = NL - k - 1; if (hi > lim) hi = lim;
            float s = 0.f;
            #pragma unroll 5
            for (int l = lo; l <= hi; l++) s += __ldg(&wk[l]);
            g_coef[i] = s;
        }
        return;
    }

    const int cp = blockIdx.x;          // output channel c'
    __shared__ float fr[384];           // fc_w row
    __shared__ float sSk[3];
    __shared__ float red[6];            // per-kk: (fc_w . conv_b), (sum fc_w)

    for (int i = tid; i < 384; i += 256) fr[i] = __ldg(&fc_w[cp * 384 + i]);

    if (warp < 3) {                     // S_k
        const float* wks[3] = {fc3_w, fc4_w, fc5_w};
        const float* w = wks[warp];
        const int n = NL - (warp + 3);
        float s = 0.f;
        for (int l = lane; l < n; l += 32) s += __ldg(&w[l]);
        #pragma unroll
        for (int off = 16; off > 0; off >>= 1)
            s += __shfl_xor_sync(0xFFFFFFFFu, s, off);
        if (lane == 0) sSk[warp] = s;
    }
    __syncthreads();

    // W2T[idx=kk*75+dj][cp] = sum_c fr[kk*128+c] * conv_w[c][dj f4]
    if (tid < 225) {
        const int kk = tid / 75;
        const int dj = tid % 75;
        const float4* conv4 = (const float4*)conv_w;
        const float* frk = fr + kk * 128;
        float4 acc = make_float4(0.f, 0.f, 0.f, 0.f);
        #pragma unroll 4
        for (int c = 0; c < 128; c++) {
            const float w = frk[c];
            const float4 v = __ldg(&conv4[c * ND4 + dj]);
            acc.x = fmaf(w, v.x, acc.x); acc.y = fmaf(w, v.y, acc.y);
            acc.z = fmaf(w, v.z, acc.z); acc.w = fmaf(w, v.w, acc.w);
        }
        g_W2T4[tid * NC + cp] = acc;
    }

    // bias2 partials
    if (warp < 3) {
        float t1 = 0.f, t2 = 0.f;
        for (int c = lane; c < 128; c += 32) {
            const float w = fr[warp * 128 + c];
            t1 = fmaf(w, __ldg(&conv_b[c]), t1);
            t2 += w;
        }
        #pragma unroll
        for (int off = 16; off > 0; off >>= 1) {
            t1 += __shfl_xor_sync(0xFFFFFFFFu, t1, off);
            t2 += __shfl_xor_sync(0xFFFFFFFFu, t2, off);
        }
        if (lane == 0) { red[warp * 2] = t1; red[warp * 2 + 1] = t2; }
    }
    __syncthreads();
    if (tid == 0) {
        const float bks[3] = {fc3_b[0], fc4_b[0], fc5_b[0]};
        float b2 = fc_b[cp];
        #pragma unroll
        for (int kk = 0; kk < 3; kk++)
            b2 += sSk[kk] * red[kk * 2] + bks[kk] * red[kk * 2 + 1];
        g_bias2[cp] = b2;
    }
}

// ---------------------------------------------------------------------------
// Kernel 1: embedding gather (hot loop unchanged from R10 best).
// Prologue now reads precomputed coefficients (1 load/thread).
// ---------------------------------------------------------------------------
__global__ __launch_bounds__(320, 3) void gather_kernel(
    const int*   __restrict__ x,
    const float* __restrict__ embed_w)
{
    const int b     = blockIdx.x >> 3;
    const int chunk = blockIdx.x & 7;

    __shared__ int    sidx[TPC];
    __shared__ float  sc[3][TPC];
    __shared__ float4 sred[WAYS][3][80];

    const int tid = threadIdx.x;
    const int d4  = tid % 80;
    const int y   = tid / 80;

    if (tid < 192) {
        const int kk = tid >> 6;
        const int tt = tid & 63;
        sc[kk][tt] = __ldg(&g_coef[kk * NL + chunk * TPC + tt]);
    } else if (tid < 256) {
        const int tt = tid - 192;
        sidx[tt] = __ldg(&x[b * NL + chunk * TPC + tt]);
    }
    __syncthreads();

    float4 a0 = make_float4(0.f, 0.f, 0.f, 0.f);
    float4 a1 = a0, a2 = a0;

    if (d4 < ND4) {
        const float4* emb4 = (const float4*)embed_w;
        #pragma unroll
        for (int bb = 0; bb < 2; bb++) {
            int    rix[8];
            float4 v[8];
            #pragma unroll
            for (int j = 0; j < 8; j++) rix[j] = sidx[y * JPER + bb * 8 + j];
            #pragma unroll
            for (int j = 0; j < 8; j++) v[j] = __ldg(&emb4[rix[j] * ND4 + d4]);
            #pragma unroll
            for (int j = 0; j < 8; j++) {
                const int jj = y * JPER + bb * 8 + j;
                const float c0 = sc[0][jj], c1 = sc[1][jj], c2 = sc[2][jj];
                a0.x = fmaf(c0, v[j].x, a0.x); a0.y = fmaf(c0, v[j].y, a0.y);
                a0.z = fmaf(c0, v[j].z, a0.z); a0.w = fmaf(c0, v[j].w, a0.w);
                a1.x = fmaf(c1, v[j].x, a1.x); a1.y = fmaf(c1, v[j].y, a1.y);
                a1.z = fmaf(c1, v[j].z, a1.z); a1.w = fmaf(c1, v[j].w, a1.w);
                a2.x = fmaf(c2, v[j].x, a2.x); a2.y = fmaf(c2, v[j].y, a2.y);
                a2.z = fmaf(c2, v[j].z, a2.z); a2.w = fmaf(c2, v[j].w, a2.w);
            }
        }
    }
    sred[y][0][d4] = a0;
    sred[y][1][d4] = a1;
    sred[y][2][d4] = a2;
    __syncthreads();

    if (tid < 240) {
        const int kk = tid / 80;
        const int dd = tid % 80;
        if (dd < ND4) {
            float4 s = sred[0][kk][dd];
            #pragma unroll
            for (int w = 1; w < WAYS; w++) {
                const float4 v = sred[w][kk][dd];
                s.x += v.x; s.y += v.y; s.z += v.z; s.w += v.w;
            }
            g_part4[((b * CH + chunk) * 3 + kk) * ND4 + dd] = s;
        }
    }
}

// ---------------------------------------------------------------------------
// Kernel 2 (final): chunk-reduce g + single fused dot out = W2T.g + bias2.
// grid (4 c'-tiles, 16 batch-tiles) = 64 blocks, 512 threads.
// Thread = (c' lane, warp = bsub*4 + q); W2T loads lane-coalesced.
// ---------------------------------------------------------------------------
__global__ __launch_bounds__(512) void final_kernel(float* __restrict__ out)
{
    __shared__ float4 sgs[4 * 225];   // reduced g for 4 batches
    __shared__ float  qp[16 * 32];    // per-warp dot partials

    const int tid  = threadIdx.x;
    const int warp = tid >> 5;
    const int lane = tid & 31;
    const int c0   = blockIdx.x * 32;
    const int b0   = blockIdx.y * 4;

    // Reduce CH chunk partials for the 4 batches
    for (int p = tid; p < 4 * 225; p += 512) {
        const int bs = p / 225;
        const int i  = p % 225;
        const float4* q = &g_part4[(b0 + bs) * (CH * 225) + i];
        float4 s = q[0];
        #pragma unroll
        for (int ch = 1; ch < CH; ch++) {
            const float4 v = q[ch * 225];
            s.x += v.x; s.y += v.y; s.z += v.z; s.w += v.w;
        }
        sgs[bs * 225 + i] = s;
    }
    __syncthreads();

    // Dot: warp -> (bsub = warp>>2, q = warp&3); q splits 225 as 57|56|56|56
    const int bsub = warp >> 2;
    const int q    = warp & 3;
    const int i0   = q * 56 + (q > 0);
    const int i1   = (q == 3) ? 225 : ((q + 1) * 56 + 1);
    float o = 0.f;
    #pragma unroll 4
    for (int i = i0; i < i1; i++) {
        const float4 w = __ldg(&g_W2T4[i * NC + c0 + lane]);  // coalesced
        const float4 g = sgs[bsub * 225 + i];                 // broadcast
        o = fmaf(w.x, g.x, o); o = fmaf(w.y, g.y, o);
        o = fmaf(w.z, g.z, o); o = fmaf(w.w, g.w, o);
    }
    qp[warp * 32 + lane] = o;
    __syncthreads();

    if (tid < 128) {
        const int bs = tid >> 5;
        const int ln = tid & 31;
        const float r = qp[(bs * 4 + 0) * 32 + ln] + qp[(bs * 4 + 1) * 32 + ln]
                      + qp[(bs * 4 + 2) * 32 + ln] + qp[(bs * 4 + 3) * 32 + ln];
        out[(b0 + bs) * NC + c0 + ln] = r + g_bias2[c0 + ln];
    }
}

// ---------------------------------------------------------------------------
extern "C" void kernel_launch(void* const* d_in, const int* in_sizes, int n_in,
                              void* d_out, int out_size) {
    const int*   x       = (const int*)  d_in[0];
    const float* embed_w = (const float*)d_in[1];
    const float* conv_w  = (const float*)d_in[2];
    const float* conv_b  = (const float*)d_in[3];
    const float* fc3_w   = (const float*)d_in[4];
    const float* fc3_b   = (const float*)d_in[5];
    const float* fc4_w   = (const float*)d_in[6];
    const float* fc4_b   = (const float*)d_in[7];
    const float* fc5_w   = (const float*)d_in[8];
    const float* fc5_b   = (const float*)d_in[9];
    const float* fc_w    = (const float*)d_in[10];
    const float* fc_b    = (const float*)d_in[11];
    float* out = (float*)d_out;

    prep_kernel<<<129, 256>>>(conv_w, conv_b, fc3_w, fc3_b, fc4_w, fc4_b,
                              fc5_w, fc5_b, fc_w, fc_b);
    gather_kernel<<<NB * CH, 320>>>(x, embed_w);
    final_kernel<<<dim3(4, 16), 512>>>(out);
}

// round 12
// speedup vs baseline: 1.6772x; 1.6772x over previous
#include <cuda_runtime.h>
#include <cuda_bf16.h>
#include <cstdint>

#define NB 64      // batch
#define NL 512     // sequence length
#define ND 300     // embed dim
#define ND4 75     // float4 lanes per row
#define NC 128     // channels
#define CH 8       // token chunks per batch
#define TPC 64     // tokens per gather block
#define WAYS 4
#define JPER 16    // tokens per way
#define ROW_BYTES (ND * 4)          // 1200, 16B-aligned
#define TILE_BYTES (TPC * ROW_BYTES) // 76800

// Scratch (__device__ globals per allocation rules)
__device__ float4 g_part4[NB * CH * 3 * ND4];  // partial g sums
__device__ float  g_h[NB * 384];               // h[b][384]

// Dyn smem layout (bytes)
#define SM_ROWS  0                   // 76800
#define SM_SRED  76800               // WAYS*3*80 f4 = 15360
#define SM_SIDX  92160               // 64 ints = 256
#define SM_SC    92416               // 3*64 floats = 768
#define SM_MBAR  93184               // 8
#define GATHER_SMEM 93200

__device__ __forceinline__ uint32_t smem_u32(const void* p) {
    uint32_t a;
    asm("{ .reg .u64 t; cvta.to.shared.u64 t, %1; cvt.u32.u64 %0, t; }"
        : "=r"(a) : "l"(p));
    return a;
}

// ---------------------------------------------------------------------------
// Kernel 1: TMA-bulk embedding gather.
// grid = NB*CH = 512 blocks, 320 threads.
// One cp.async.bulk per embedding row (64/block) replaces 4800 LDG.128.
// Coefs computed while copies are in flight; weighted sums read from smem.
// ---------------------------------------------------------------------------
__global__ __launch_bounds__(320) void gather_kernel(
    const int*   __restrict__ x,
    const float* __restrict__ embed_w,
    const float* __restrict__ fc3_w,
    const float* __restrict__ fc4_w,
    const float* __restrict__ fc5_w)
{
    extern __shared__ char smem[];
    float*  rows  = (float*)(smem + SM_ROWS);
    float4* sred  = (float4*)(smem + SM_SRED);    // [WAYS][3][80]
    int*    sidx  = (int*)(smem + SM_SIDX);
    float*  sc    = (float*)(smem + SM_SC);       // [3][64]
    const uint32_t mbar = smem_u32(smem + SM_MBAR);
    const uint32_t rows_s = smem_u32(rows);

    const int b     = blockIdx.x >> 3;
    const int chunk = blockIdx.x & 7;
    const int tid   = threadIdx.x;
    const int d4    = tid % 80;
    const int y     = tid / 80;

    // mbarrier init + index load
    if (tid == 0) {
        asm volatile("mbarrier.init.shared.b64 [%0], 1;" :: "r"(mbar) : "memory");
    }
    if (tid < TPC)
        sidx[tid] = __ldg(&x[b * NL + chunk * TPC + tid]);
    asm volatile("fence.proxy.async.shared::cta;" ::: "memory");
    __syncthreads();

    // Issue bulk copies (threads 0..63: one row each) + expect_tx (tid 0)
    if (tid == 0) {
        asm volatile("mbarrier.arrive.expect_tx.shared.b64 _, [%0], %1;"
                     :: "r"(mbar), "r"((uint32_t)TILE_BYTES) : "memory");
    }
    if (tid < TPC) {
        const char* src = (const char*)embed_w + (size_t)sidx[tid] * ROW_BYTES;
        const uint32_t dst = rows_s + tid * ROW_BYTES;
        asm volatile(
            "cp.async.bulk.shared::cta.global.mbarrier::complete_tx::bytes "
            "[%0], [%1], %2, [%3];"
            :: "r"(dst), "l"(src), "r"((uint32_t)ROW_BYTES), "r"(mbar)
            : "memory");
    }

    // Overlap: compute window coefficients while TMA is in flight
    if (tid >= 64 && tid < 256) {
        const int kk = (tid - 64) >> 6;
        const int tt = (tid - 64) & 63;
        const int t  = chunk * TPC + tt;
        const float* wk = (kk == 0) ? fc3_w : (kk == 1) ? fc4_w : fc5_w;
        const int k = kk + 3;
        int lo = t - k + 1; if (lo < 0) lo = 0;
        int hi = t; const int lim = NL - k - 1; if (hi > lim) hi = lim;
        float s = 0.f;
        #pragma unroll 5
        for (int l = lo; l <= hi; l++) s += __ldg(&wk[l]);
        sc[kk * TPC + tt] = s;
    }
    __syncthreads();   // sc visible to everyone

    // Wait for TMA completion (phase 0), acquire
    {
        uint32_t done;
        asm volatile(
            "{\n\t.reg .pred p;\n\t"
            "mbarrier.try_wait.parity.acquire.cta.shared::cta.b64 p, [%1], 0;\n\t"
            "selp.b32 %0, 1, 0, p;\n\t}"
            : "=r"(done) : "r"(mbar) : "memory");
        if (!done) {
            asm volatile(
                "{\n\t.reg .pred P1;\n\t"
                "WL_%=:\n\t"
                "mbarrier.try_wait.parity.acquire.cta.shared::cta.b64 P1, [%0], 0, 0x989680;\n\t"
                "@P1 bra.uni WD_%=;\n\t"
                "bra.uni WL_%=;\n\t"
                "WD_%=:\n\t}"
                :: "r"(mbar) : "memory");
        }
    }

    // Weighted sums from smem rows
    float4 a0 = make_float4(0.f, 0.f, 0.f, 0.f);
    float4 a1 = a0, a2 = a0;

    if (d4 < ND4) {
        const float4* rows4 = (const float4*)rows;
        #pragma unroll 4
        for (int j = 0; j < JPER; j++) {
            const int jj = y * JPER + j;
            const float4 v = rows4[jj * ND4 + d4];
            const float c0 = sc[0 * TPC + jj];
            const float c1 = sc[1 * TPC + jj];
            const float c2 = sc[2 * TPC + jj];
            a0.x = fmaf(c0, v.x, a0.x); a0.y = fmaf(c0, v.y, a0.y);
            a0.z = fmaf(c0, v.z, a0.z); a0.w = fmaf(c0, v.w, a0.w);
            a1.x = fmaf(c1, v.x, a1.x); a1.y = fmaf(c1, v.y, a1.y);
            a1.z = fmaf(c1, v.z, a1.z); a1.w = fmaf(c1, v.w, a1.w);
            a2.x = fmaf(c2, v.x, a2.x); a2.y = fmaf(c2, v.y, a2.y);
            a2.z = fmaf(c2, v.z, a2.z); a2.w = fmaf(c2, v.w, a2.w);
        }
    }
    sred[(y * 3 + 0) * 80 + d4] = a0;
    sred[(y * 3 + 1) * 80 + d4] = a1;
    sred[(y * 3 + 2) * 80 + d4] = a2;
    __syncthreads();

    if (tid < 240) {
        const int kk = tid / 80;
        const int dd = tid % 80;
        if (dd < ND4) {
            float4 s = sred[(0 * 3 + kk) * 80 + dd];
            #pragma unroll
            for (int w = 1; w < WAYS; w++) {
                const float4 v = sred[(w * 3 + kk) * 80 + dd];
                s.x += v.x; s.y += v.y; s.z += v.z; s.w += v.w;
            }
            g_part4[((b * CH + chunk) * 3 + kk) * ND4 + dd] = s;
        }
    }
}

// ---------------------------------------------------------------------------
// Kernel 2: sim. grid (4 ctiles, 64 batches) = 256 blocks, 128 threads.
// (unchanged from R10 best)
// ---------------------------------------------------------------------------
__global__ __launch_bounds__(128) void sim_kernel(
    const float* __restrict__ conv_w,
    const float* __restrict__ conv_b,
    const float* __restrict__ fc3_w,
    const float* __restrict__ fc3_b,
    const float* __restrict__ fc4_w,
    const float* __restrict__ fc4_b,
    const float* __restrict__ fc5_w,
    const float* __restrict__ fc5_b)
{
    __shared__ float4 cw_s[32 * ND4];
    __shared__ float4 sg[3 * ND4];
    __shared__ float  qp[4 * 96];
    __shared__ float  sSk[3];

    const int tid  = threadIdx.x;
    const int warp = tid >> 5;
    const int lane = tid & 31;
    const int ct   = blockIdx.x;
    const int b    = blockIdx.y;
    const int c0   = ct * 32;

    if (warp < 3) {
        const float* wks[3] = {fc3_w, fc4_w, fc5_w};
        const float* w = wks[warp];
        const int n = NL - (warp + 3);
        float s = 0.f;
        for (int l = lane; l < n; l += 32) s += w[l];
        #pragma unroll
        for (int off = 16; off > 0; off >>= 1)
            s += __shfl_xor_sync(0xFFFFFFFFu, s, off);
        if (lane == 0) sSk[warp] = s;
    }

    {
        const float4* cwg = (const float4*)conv_w;
        #pragma unroll 4
        for (int j = tid; j < 32 * ND4; j += 128)
            cw_s[j] = __ldg(&cwg[c0 * ND4 + j]);
    }
    #pragma unroll
    for (int i = tid; i < 225; i += 128) {
        const float4* p = &g_part4[b * (CH * 225) + i];
        float4 s = p[0];
        #pragma unroll
        for (int ch = 1; ch < CH; ch++) {
            const float4 v = p[ch * 225];
            s.x += v.x; s.y += v.y; s.z += v.z; s.w += v.w;
        }
        sg[i] = s;
    }
    __syncthreads();

    const int c = lane;
    const int q = warp;
    {
        const int i0 = q * 19;
        const int i1 = (q == 3) ? ND4 : (i0 + 19);
        float s0 = 0.f, s1 = 0.f, s2 = 0.f;
        #pragma unroll 4
        for (int i = i0; i < i1; i++) {
            const float4 w  = cw_s[c * ND4 + i];
            const float4 g0 = sg[i];
            const float4 g1 = sg[75 + i];
            const float4 g2 = sg[150 + i];
            s0 = fmaf(w.x, g0.x, s0); s0 = fmaf(w.y, g0.y, s0);
            s0 = fmaf(w.z, g0.z, s0); s0 = fmaf(w.w, g0.w, s0);
            s1 = fmaf(w.x, g1.x, s1); s1 = fmaf(w.y, g1.y, s1);
            s1 = fmaf(w.z, g1.z, s1); s1 = fmaf(w.w, g1.w, s1);
            s2 = fmaf(w.x, g2.x, s2); s2 = fmaf(w.y, g2.y, s2);
            s2 = fmaf(w.z, g2.z, s2); s2 = fmaf(w.w, g2.w, s2);
        }
        qp[q * 96 + 0 * 32 + c] = s0;
        qp[q * 96 + 1 * 32 + c] = s1;
        qp[q * 96 + 2 * 32 + c] = s2;
    }
    __syncthreads();

    if (tid < 96) {
        const int kk = tid / 32;
        const int cc = tid % 32;
        float h = qp[0 * 96 + kk * 32 + cc] + qp[1 * 96 + kk * 32 + cc]
                + qp[2 * 96 + kk * 32 + cc] + qp[3 * 96 + kk * 32 + cc];
        const float bk = (kk == 0) ? fc3_b[0] : (kk == 1) ? fc4_b[0] : fc5_b[0];
        h += conv_b[c0 + cc] * sSk[kk] + bk;
        g_h[b * 384 + kk * NC + c0 + cc] = h;
    }
}

// ---------------------------------------------------------------------------
// Kernel 3: fc. grid (4 cotiles, 64 batches) = 256 blocks, 128 threads.
// (unchanged from R10 best)
// ---------------------------------------------------------------------------
__global__ __launch_bounds__(128) void fc_kernel(
    const float* __restrict__ fc_w,
    const float* __restrict__ fc_b,
    float* __restrict__ out)
{
    __shared__ float4 fw_s[32 * 97];
    __shared__ float4 sh[96];
    __shared__ float  qp[128];

    const int tid = threadIdx.x;
    const int ct  = blockIdx.x;
    const int b   = blockIdx.y;
    const int c0  = ct * 32;

    {
        const float4* fwg = (const float4*)fc_w;
        #pragma unroll 4
        for (int j = tid; j < 32 * 96; j += 128) {
            const int r = j / 96, i = j % 96;
            fw_s[r * 97 + i] = __ldg(&fwg[c0 * 96 + j]);
        }
        if (tid < 96) sh[tid] = ((const float4*)g_h)[b * 96 + tid];
    }
    __syncthreads();

    const int co = tid & 31;
    const int q  = tid >> 5;
    {
        float o = 0.f;
        #pragma unroll 4
        for (int i = q * 24; i < q * 24 + 24; i++) {
            const float4 w = fw_s[co * 97 + i];
            const float4 h = sh[i];
            o = fmaf(w.x, h.x, o); o = fmaf(w.y, h.y, o);
            o = fmaf(w.z, h.z, o); o = fmaf(w.w, h.w, o);
        }
        qp[q * 32 + co] = o;
    }
    __syncthreads();

    if (tid < 32)
        out[b * NC + c0 + tid] = qp[tid] + qp[32 + tid] + qp[64 + tid]
                               + qp[96 + tid] + fc_b[c0 + tid];
}

// ---------------------------------------------------------------------------
extern "C" void kernel_launch(void* const* d_in, const int* in_sizes, int n_in,
                              void* d_out, int out_size) {
    const int*   x       = (const int*)  d_in[0];
    const float* embed_w = (const float*)d_in[1];
    const float* conv_w  = (const float*)d_in[2];
    const float* conv_b  = (const float*)d_in[3];
    const float* fc3_w   = (const float*)d_in[4];
    const float* fc3_b   = (const float*)d_in[5];
    const float* fc4_w   = (const float*)d_in[6];
    const float* fc4_b   = (const float*)d_in[7];
    const float* fc5_w   = (const float*)d_in[8];
    const float* fc5_b   = (const float*)d_in[9];
    const float* fc_w    = (const float*)d_in[10];
    const float* fc_b    = (const float*)d_in[11];
    float* out = (float*)d_out;

    static int smem_set = 0;
    if (!smem_set) {
        cudaFuncSetAttribute(gather_kernel,
                             cudaFuncAttributeMaxDynamicSharedMemorySize, GATHER_SMEM);
        smem_set = 1;
    }

    gather_kernel<<<NB * CH, 320, GATHER_SMEM>>>(x, embed_w, fc3_w, fc4_w, fc5_w);
    sim_kernel<<<dim3(4, NB), 128>>>(conv_w, conv_b, fc3_w, fc3_b,
                                     fc4_w, fc4_b, fc5_w, fc5_b);
    fc_kernel<<<dim3(4, NB), 128>>>(fc_w, fc_b, out);
}